// round 12
// baseline (speedup 1.0000x reference)
#include <cuda_runtime.h>
#include <cstdint>

using ull = unsigned long long;

static constexpr int D = 256, H = 512, NCLS = 10, TPTS = 8;
static constexpr int ROWS = 16, THREADS = 256;
static constexpr int STR = 20;                 // padded floats per transposed row (16 used)
// smem layout (floats)
static constexpr int OFF_YT  = 0;              // 256*20 = 5120
static constexpr int OFF_YST = 256 * STR;      // stage input / GEMM2 scratch A
static constexpr int OFF_HT  = OFF_YST + 256 * STR;   // h / gemm1 scratch / gemm2 scratch B
static constexpr int OFF_KT  = OFF_HT + 512 * STR;
static constexpr int KT_STRIDE = 256 * STR;    // 5120 floats per k-stage
static constexpr int SMEM_FLOATS = OFF_KT + 6 * KT_STRIDE;   // 51200
static constexpr int SMEM_BYTES  = SMEM_FLOATS * 4;          // 204800
static constexpr int SLOT = 68;                // scratch slot stride (64 used, pad 4)

__device__ __forceinline__ ull fma2(ull a, ull b, ull c) {
    ull d; asm("fma.rn.f32x2 %0, %1, %2, %3;" : "=l"(d) : "l"(a), "l"(b), "l"(c)); return d;
}
__device__ __forceinline__ ull add2(ull a, ull b) {
    ull d; asm("add.rn.f32x2 %0, %1, %2;" : "=l"(d) : "l"(a), "l"(b)); return d;
}
__device__ __forceinline__ ull pack2(float x) {
    ull r; asm("mov.b64 %0, {%1, %1};" : "=l"(r) : "f"(x)); return r;
}
__device__ __forceinline__ float2 u2f(ull v) {
    float2 r; asm("mov.b64 {%0, %1}, %2;" : "=f"(r.x), "=f"(r.y) : "l"(v)); return r;
}
__device__ __forceinline__ float tanhfast(float x) {
    float e = __expf(2.0f * x);
    return 1.0f - __fdividef(2.0f, e + 1.0f);
}

// 4-k block: R=16 rows (8 packed pairs), C=4 cols; weights preloaded w[4]
__device__ __forceinline__ void block4(const float* actT, const float4* w, ull (&acc)[8][4]) {
#pragma unroll
    for (int j = 0; j < 4; j++) {
        const float* row = actT + j * STR;
        ulonglong2 a01 = *(const ulonglong2*)(row);
        ulonglong2 a23 = *(const ulonglong2*)(row + 4);
        ulonglong2 a45 = *(const ulonglong2*)(row + 8);
        ulonglong2 a67 = *(const ulonglong2*)(row + 12);
        ull a[8] = {a01.x, a01.y, a23.x, a23.y, a45.x, a45.y, a67.x, a67.y};
        float4 wv = w[j];
        ull b0 = pack2(wv.x), b1 = pack2(wv.y), b2 = pack2(wv.z), b3 = pack2(wv.w);
#pragma unroll
        for (int p = 0; p < 8; p++) {
            acc[p][0] = fma2(a[p], b0, acc[p][0]);
            acc[p][1] = fma2(a[p], b1, acc[p][1]);
            acc[p][2] = fma2(a[p], b2, acc[p][2]);
            acc[p][3] = fma2(a[p], b3, acc[p][3]);
        }
    }
}

// 128 k's; acts at actT (k*STR), weights from gmem (row stride ws), 4 cols/LDG.128
__device__ __forceinline__ void gloop(const float* actT, const float* wp, int ws,
                                      ull (&acc)[8][4]) {
    float4 wA[4], wB[4];
#pragma unroll
    for (int j = 0; j < 4; j++) wA[j] = *(const float4*)(wp + j * ws);
#pragma unroll 1
    for (int b = 0; b < 32; b += 2) {
        const float* w1p = wp + (b + 1) * 4 * ws;
#pragma unroll
        for (int j = 0; j < 4; j++) wB[j] = *(const float4*)(w1p + j * ws);
        block4(actT + b * 4 * STR, wA, acc);
        if (b + 2 < 32) {
            const float* w2p = wp + (b + 2) * 4 * ws;
#pragma unroll
            for (int j = 0; j < 4; j++) wA[j] = *(const float4*)(w2p + j * ws);
        }
        block4(actT + (b + 1) * 4 * STR, wB, acc);
    }
}

// scratch slot: 64 floats (16 rows x 4 cols), stride SLOT=68 (≡4 mod 32 banks)
__device__ __forceinline__ void sts_acc(float* base, const ull (&acc)[8][4]) {
#pragma unroll
    for (int q = 0; q < 4; q++) {
        ulonglong2 o;
        o.x = acc[0][q]; o.y = acc[1][q]; *(ulonglong2*)(base + q * 16)      = o;
        o.x = acc[2][q]; o.y = acc[3][q]; *(ulonglong2*)(base + q * 16 + 4)  = o;
        o.x = acc[4][q]; o.y = acc[5][q]; *(ulonglong2*)(base + q * 16 + 8)  = o;
        o.x = acc[6][q]; o.y = acc[7][q]; *(ulonglong2*)(base + q * 16 + 12) = o;
    }
}
__device__ __forceinline__ void lds_add_acc(const float* base, ull (&acc)[8][4]) {
#pragma unroll
    for (int q = 0; q < 4; q++) {
        ulonglong2 v0 = *(const ulonglong2*)(base + q * 16);
        ulonglong2 v1 = *(const ulonglong2*)(base + q * 16 + 4);
        ulonglong2 v2 = *(const ulonglong2*)(base + q * 16 + 8);
        ulonglong2 v3 = *(const ulonglong2*)(base + q * 16 + 12);
        acc[0][q] = add2(acc[0][q], v0.x); acc[1][q] = add2(acc[1][q], v0.y);
        acc[2][q] = add2(acc[2][q], v1.x); acc[3][q] = add2(acc[3][q], v1.y);
        acc[4][q] = add2(acc[4][q], v2.x); acc[5][q] = add2(acc[5][q], v2.y);
        acc[6][q] = add2(acc[6][q], v3.x); acc[7][q] = add2(acc[7][q], v3.y);
    }
}

// GEMM1: hT = tanh(actT^T @ W1 + b1). K-split 2 (kh), all 16 rows, cols c0..c0+3.
// kh1 stages partials into hT region (dead), kh0 reduces + tanh + writes hT.
__device__ __forceinline__ void gemm1(const float* actT, const float* W1g, float* hT,
                                      const float (&b1r)[4], int kh, int cg, int c0) {
    ull acc[8][4];
#pragma unroll
    for (int p = 0; p < 8; p++)
#pragma unroll
        for (int q = 0; q < 4; q++) acc[p][q] = 0ULL;
    gloop(actT + kh * 128 * STR, W1g + (size_t)kh * 128 * H + c0, H, acc);

    if (kh == 1) sts_acc(hT + cg * SLOT, acc);
    __syncthreads();
    if (kh == 0) lds_add_acc(hT + cg * SLOT, acc);
    __syncthreads();            // WAR: scratch reads done before final hT writes
    if (kh == 0) {
        const int rot = cg & 3;
#pragma unroll
        for (int i = 0; i < 4; i++) {
            int q = (i + rot) & 3;
            float b = b1r[q];
            float* hc = hT + (c0 + q) * STR;
#pragma unroll
            for (int g = 0; g < 4; g++) {
                float2 fa = u2f(acc[2 * g][q]), fb = u2f(acc[2 * g + 1][q]);
                float4 v;
                v.x = tanhfast(fa.x + b); v.y = tanhfast(fa.y + b);
                v.z = tanhfast(fb.x + b); v.w = tanhfast(fb.y + b);
                *(float4*)(hc + 4 * g) = v;
            }
        }
    }
    __syncthreads();            // hT final before gemm2 reads
}

// GEMM2: kdst = hT^T @ W2 + b2. K-split 4 (kq), all 16 rows, cols c2..c2+3.
// Tree: kq1->A(ysT), kq3->B(hT, dead post-gloop); kq0+=A, kq2+=B->B; kq0+=B.
__device__ __forceinline__ void gemm2(float* hT, const float* W2g, float* A,
                                      float* kdst, const ull (&b2p)[4],
                                      int kq, int cg2, int c2) {
    ull acc[8][4];
#pragma unroll
    for (int p = 0; p < 8; p++)
#pragma unroll
        for (int q = 0; q < 4; q++) acc[p][q] = 0ULL;
    gloop(hT + kq * 128 * STR, W2g + (size_t)kq * 128 * D + c2, D, acc);
    __syncthreads();            // all hT reads done; hT reusable as scratch B

    if (kq == 1) sts_acc(A + cg2 * SLOT, acc);
    if (kq == 3) sts_acc(hT + cg2 * SLOT, acc);
    __syncthreads();
    if (kq == 0) lds_add_acc(A + cg2 * SLOT, acc);
    if (kq == 2) { lds_add_acc(hT + cg2 * SLOT, acc); sts_acc(hT + cg2 * SLOT, acc); }
    __syncthreads();
    if (kq == 0) {
        lds_add_acc(hT + cg2 * SLOT, acc);
        const int rot = cg2 & 3;
#pragma unroll
        for (int i = 0; i < 4; i++) {
            int q = (i + rot) & 3;
            float* kc = kdst + (c2 + q) * STR;
#pragma unroll
            for (int g = 0; g < 4; g++) {
                ulonglong2 o;
                o.x = add2(acc[2 * g][q], b2p[q]);
                o.y = add2(acc[2 * g + 1][q], b2p[q]);
                *(ulonglong2*)(kc + 4 * g) = o;
            }
        }
    }
    __syncthreads();
}

// dst col d = ysrc col d + sum_{j<cnt} cf[j] * kT[j] col d   (thread d = tid)
__device__ __forceinline__ void combine(float* dst, const float* ysrc, const float* kbase,
                                        const float (&cf)[6], int cnt, int tid) {
    const int off = tid * STR;
    ulonglong2 e01 = *(const ulonglong2*)(ysrc + off);
    ulonglong2 e23 = *(const ulonglong2*)(ysrc + off + 4);
    ulonglong2 e45 = *(const ulonglong2*)(ysrc + off + 8);
    ulonglong2 e67 = *(const ulonglong2*)(ysrc + off + 12);
    ull e[8] = {e01.x, e01.y, e23.x, e23.y, e45.x, e45.y, e67.x, e67.y};
#pragma unroll
    for (int j = 0; j < 6; j++) {
        if (j < cnt) {
            ull c = pack2(cf[j]);
            const float* kr = kbase + j * KT_STRIDE + off;
            ulonglong2 k01 = *(const ulonglong2*)(kr);
            ulonglong2 k23 = *(const ulonglong2*)(kr + 4);
            ulonglong2 k45 = *(const ulonglong2*)(kr + 8);
            ulonglong2 k67 = *(const ulonglong2*)(kr + 12);
            e[0] = fma2(c, k01.x, e[0]); e[1] = fma2(c, k01.y, e[1]);
            e[2] = fma2(c, k23.x, e[2]); e[3] = fma2(c, k23.y, e[3]);
            e[4] = fma2(c, k45.x, e[4]); e[5] = fma2(c, k45.y, e[5]);
            e[6] = fma2(c, k67.x, e[6]); e[7] = fma2(c, k67.y, e[7]);
        }
    }
    ulonglong2 o;
    o.x = e[0]; o.y = e[1]; *(ulonglong2*)(dst + off)      = o;
    o.x = e[2]; o.y = e[3]; *(ulonglong2*)(dst + off + 4)  = o;
    o.x = e[4]; o.y = e[5]; *(ulonglong2*)(dst + off + 8)  = o;
    o.x = e[6]; o.y = e[7]; *(ulonglong2*)(dst + off + 12) = o;
}

__global__ void __launch_bounds__(THREADS, 1)
node_ode_kernel(const float* __restrict__ x0, const float* __restrict__ t,
                const float* __restrict__ W1, const float* __restrict__ b1,
                const float* __restrict__ W2, const float* __restrict__ b2,
                const float* __restrict__ Wc1, const float* __restrict__ bc1,
                const float* __restrict__ Wc2, const float* __restrict__ bc2,
                float* __restrict__ out) {
    extern __shared__ float sm[];
    float* yT  = sm + OFF_YT;
    float* ysT = sm + OFF_YST;   // stage input / GEMM2 scratch A
    float* hT  = sm + OFF_HT;    // h / gemm1 scratch / gemm2 scratch B
    float* kT  = sm + OFF_KT;

    const int tid = threadIdx.x;
    // GEMM1 mapping: K-split 2, 128 column-groups
    const int kh  = tid >> 7;
    const int cg  = tid & 127;
    const int c0  = cg * 4;
    // GEMM2 mapping: K-split 4, 64 column-groups
    const int kq  = tid >> 6;
    const int cg2 = tid & 63;
    const int c2  = cg2 * 4;
    const int rowBase = blockIdx.x * ROWS;

    // transpose x0 tile into yT[k][row]
    {
        const int d = tid;
#pragma unroll
        for (int r = 0; r < ROWS; r++)
            yT[d * STR + r] = x0[(size_t)(rowBase + r) * D + d];
    }

    float b1r[4];
    {
        float4 u = *(const float4*)(b1 + c0);
        b1r[0] = u.x; b1r[1] = u.y; b1r[2] = u.z; b1r[3] = u.w;
    }
    ull b2p[4];
#pragma unroll
    for (int q = 0; q < 4; q++) b2p[q] = pack2(b2[c2 + q]);

    float tv[TPTS];
#pragma unroll
    for (int i = 0; i < TPTS; i++) tv[i] = t[i];

    __syncthreads();

    // dopri5 tableau
    const float A1[1] = {0.2f};
    const float A2[2] = {3.0f/40.0f, 9.0f/40.0f};
    const float A3[3] = {44.0f/45.0f, -56.0f/15.0f, 32.0f/9.0f};
    const float A4[4] = {19372.0f/6561.0f, -25360.0f/2187.0f, 64448.0f/6561.0f, -212.0f/729.0f};
    const float A5[5] = {9017.0f/3168.0f, -355.0f/33.0f, 46732.0f/5247.0f, 49.0f/176.0f, -5103.0f/18656.0f};
    const float B6[6] = {35.0f/384.0f, 0.0f, 500.0f/1113.0f, 125.0f/192.0f, -2187.0f/6784.0f, 11.0f/84.0f};
    const float* Arows[5] = {A1, A2, A3, A4, A5};

#pragma unroll 1
    for (int iv = 0; iv < TPTS - 1; iv++) {
        const float dt = (tv[iv + 1] - tv[iv]) * 0.25f;   // SUBSTEPS = 4
#pragma unroll 1
        for (int ss = 0; ss < 4; ss++) {
            // stage 1: k1 = f(y)
            gemm1(yT, W1, hT, b1r, kh, cg, c0);
            gemm2(hT, W2, ysT, kT, b2p, kq, cg2, c2);
            // stages 2..6
#pragma unroll 1
            for (int s = 1; s < 6; s++) {
                float cf[6];
#pragma unroll
                for (int j = 0; j < 6; j++) cf[j] = (j < s) ? dt * Arows[s - 1][j] : 0.0f;
                combine(ysT, yT, kT, cf, s, tid);
                __syncthreads();
                gemm1(ysT, W1, hT, b1r, kh, cg, c0);
                gemm2(hT, W2, ysT, kT + s * KT_STRIDE, b2p, kq, cg2, c2);
            }
            // final update: y += dt * sum b_i k_i
            float cf[6];
#pragma unroll
            for (int j = 0; j < 6; j++) cf[j] = dt * B6[j];
            combine(yT, yT, kT, cf, 6, tid);
            __syncthreads();
        }
    }

    // classifier head: h2 = relu(y @ Wc1 + bc1) -> reuse hT as [16 x 64]
    {
        const int r  = tid >> 4;
        const int cc = (tid & 15) * 4;
        float4 bb = *(const float4*)(bc1 + cc);
        float a0 = bb.x, a1 = bb.y, a2 = bb.z, a3 = bb.w;
#pragma unroll 4
        for (int k = 0; k < D; k++) {
            float a = yT[k * STR + r];
            float4 w = *(const float4*)(Wc1 + k * 64 + cc);
            a0 = fmaf(a, w.x, a0); a1 = fmaf(a, w.y, a1);
            a2 = fmaf(a, w.z, a2); a3 = fmaf(a, w.w, a3);
        }
        float4 o;
        o.x = fmaxf(a0, 0.0f); o.y = fmaxf(a1, 0.0f);
        o.z = fmaxf(a2, 0.0f); o.w = fmaxf(a3, 0.0f);
        *(float4*)(hT + r * 64 + cc) = o;
    }
    __syncthreads();
    // logits = h2 @ Wc2 + bc2, [16 x 10]
    if (tid < ROWS * NCLS) {
        const int r = tid / NCLS;
        const int c = tid - r * NCLS;
        float s = bc2[c];
#pragma unroll 8
        for (int k = 0; k < 64; k++)
            s = fmaf(hT[r * 64 + k], Wc2[k * NCLS + c], s);
        out[(size_t)(rowBase + r) * NCLS + c] = s;
    }
}

extern "C" void kernel_launch(void* const* d_in, const int* in_sizes, int n_in,
                              void* d_out, int out_size) {
    const float* x0  = (const float*)d_in[0];
    const float* t   = (const float*)d_in[1];
    const float* W1  = (const float*)d_in[2];
    const float* b1  = (const float*)d_in[3];
    const float* W2  = (const float*)d_in[4];
    const float* b2  = (const float*)d_in[5];
    const float* Wc1 = (const float*)d_in[6];
    const float* bc1 = (const float*)d_in[7];
    const float* Wc2 = (const float*)d_in[8];
    const float* bc2 = (const float*)d_in[9];
    float* out = (float*)d_out;

    static bool attr_set = false;
    if (!attr_set) {
        cudaFuncSetAttribute(node_ode_kernel,
                             cudaFuncAttributeMaxDynamicSharedMemorySize, SMEM_BYTES);
        attr_set = true;
    }
    node_ode_kernel<<<2048 / ROWS, THREADS, SMEM_BYTES>>>(
        x0, t, W1, b1, W2, b2, Wc1, bc1, Wc2, bc2, out);
}

// round 13
// speedup vs baseline: 3.0825x; 3.0825x over previous
#include <cuda_runtime.h>
#include <cstdint>

using ull = unsigned long long;

static constexpr int D = 256, H = 512, NCLS = 10, TPTS = 8;
static constexpr int ROWS = 16, THREADS = 512;
static constexpr int STR = 20;                 // padded floats per transposed row (16 used)
// smem layout (floats)
static constexpr int OFF_YT  = 0;              // 256*20 = 5120
static constexpr int OFF_YST = 256 * STR;      // stage input / GEMM2 scratch A
static constexpr int OFF_HT  = OFF_YST + 256 * STR;   // h / gemm1 scratch / gemm2 scratch B
static constexpr int OFF_KT  = OFF_HT + 512 * STR;
static constexpr int KT_STRIDE = 256 * STR;    // 5120 floats per k-stage
static constexpr int SMEM_FLOATS = OFF_KT + 6 * KT_STRIDE;   // 51200
static constexpr int SMEM_BYTES  = SMEM_FLOATS * 4;          // 204800
static constexpr int SLOT = 36;                // scratch slot stride (32 used, ≡4 mod 32 banks)

__device__ __forceinline__ ull fma2(ull a, ull b, ull c) {
    ull d; asm("fma.rn.f32x2 %0, %1, %2, %3;" : "=l"(d) : "l"(a), "l"(b), "l"(c)); return d;
}
__device__ __forceinline__ ull add2(ull a, ull b) {
    ull d; asm("add.rn.f32x2 %0, %1, %2;" : "=l"(d) : "l"(a), "l"(b)); return d;
}
__device__ __forceinline__ ull pack2(float x) {
    ull r; asm("mov.b64 %0, {%1, %1};" : "=l"(r) : "f"(x)); return r;
}
__device__ __forceinline__ float2 u2f(ull v) {
    float2 r; asm("mov.b64 {%0, %1}, %2;" : "=f"(r.x), "=f"(r.y) : "l"(v)); return r;
}
__device__ __forceinline__ float tanhfast(float x) {
    float e = __expf(2.0f * x);
    return 1.0f - __fdividef(2.0f, e + 1.0f);
}

// 4-k block: R=8 rows (4 packed pairs), C=4 cols; weights preloaded w[4]
__device__ __forceinline__ void blk4(const float* actT, const float4* w, ull (&acc)[4][4]) {
#pragma unroll
    for (int j = 0; j < 4; j++) {
        const float* row = actT + j * STR;
        ulonglong2 a01 = *(const ulonglong2*)(row);
        ulonglong2 a23 = *(const ulonglong2*)(row + 4);
        ull a[4] = {a01.x, a01.y, a23.x, a23.y};
        float4 wv = w[j];
        ull b0 = pack2(wv.x), b1 = pack2(wv.y), b2 = pack2(wv.z), b3 = pack2(wv.w);
#pragma unroll
        for (int p = 0; p < 4; p++) {
            acc[p][0] = fma2(a[p], b0, acc[p][0]);
            acc[p][1] = fma2(a[p], b1, acc[p][1]);
            acc[p][2] = fma2(a[p], b2, acc[p][2]);
            acc[p][3] = fma2(a[p], b3, acc[p][3]);
        }
    }
}

// 128 k's; acts at actT (k*STR), weights from gmem (row stride ws), 1 LDG.128/k
__device__ __forceinline__ void gloop(const float* actT, const float* wp, int ws,
                                      ull (&acc)[4][4]) {
    float4 wA[4], wB[4];
#pragma unroll
    for (int j = 0; j < 4; j++) wA[j] = *(const float4*)(wp + j * ws);
#pragma unroll 1
    for (int b = 0; b < 32; b += 2) {
        const float* w1p = wp + (b + 1) * 4 * ws;
#pragma unroll
        for (int j = 0; j < 4; j++) wB[j] = *(const float4*)(w1p + j * ws);
        blk4(actT + b * 4 * STR, wA, acc);
        if (b + 2 < 32) {
            const float* w2p = wp + (b + 2) * 4 * ws;
#pragma unroll
            for (int j = 0; j < 4; j++) wA[j] = *(const float4*)(w2p + j * ws);
        }
        blk4(actT + (b + 1) * 4 * STR, wB, acc);
    }
}

// scratch slot: 32 floats (8 rows x 4 cols)
__device__ __forceinline__ void sts_acc(float* base, const ull (&acc)[4][4]) {
#pragma unroll
    for (int q = 0; q < 4; q++) {
        ulonglong2 o;
        o.x = acc[0][q]; o.y = acc[1][q]; *(ulonglong2*)(base + q * 8)     = o;
        o.x = acc[2][q]; o.y = acc[3][q]; *(ulonglong2*)(base + q * 8 + 4) = o;
    }
}
__device__ __forceinline__ void lds_add_acc(const float* base, ull (&acc)[4][4]) {
#pragma unroll
    for (int q = 0; q < 4; q++) {
        ulonglong2 v0 = *(const ulonglong2*)(base + q * 8);
        ulonglong2 v1 = *(const ulonglong2*)(base + q * 8 + 4);
        acc[0][q] = add2(acc[0][q], v0.x); acc[1][q] = add2(acc[1][q], v0.y);
        acc[2][q] = add2(acc[2][q], v1.x); acc[3][q] = add2(acc[3][q], v1.y);
    }
}

// GEMM1: hT = tanh(actT^T @ W1 + b1). K-split 2 (kh), rows rg*8..+8, cols c0..+3.
// kh1 stages partials into hT region (dead, 256 slots x 36 = 9216 <= 10240).
__device__ __forceinline__ void gemm1(const float* actT, const float* W1g, float* hT,
                                      const float (&b1r)[4], int kh, int rg, int cg,
                                      int c0, int slot1) {
    ull acc[4][4];
#pragma unroll
    for (int p = 0; p < 4; p++)
#pragma unroll
        for (int q = 0; q < 4; q++) acc[p][q] = 0ULL;
    gloop(actT + kh * 128 * STR + rg * 8, W1g + (size_t)kh * 128 * H + c0, H, acc);

    if (kh == 1) sts_acc(hT + slot1 * SLOT, acc);
    __syncthreads();
    if (kh == 0) lds_add_acc(hT + slot1 * SLOT, acc);
    __syncthreads();            // WAR: scratch reads done before final hT writes
    if (kh == 0) {
        const int rot = cg & 3;
#pragma unroll
        for (int i = 0; i < 4; i++) {
            int q = (i + rot) & 3;
            float b = b1r[q];
            float2 fa = u2f(acc[0][q]), fb = u2f(acc[1][q]);
            float2 fc = u2f(acc[2][q]), fd = u2f(acc[3][q]);
            float4 v0, v1;
            v0.x = tanhfast(fa.x + b); v0.y = tanhfast(fa.y + b);
            v0.z = tanhfast(fb.x + b); v0.w = tanhfast(fb.y + b);
            v1.x = tanhfast(fc.x + b); v1.y = tanhfast(fc.y + b);
            v1.z = tanhfast(fd.x + b); v1.w = tanhfast(fd.y + b);
            float* hc = hT + (c0 + q) * STR + rg * 8;
            *(float4*)(hc)     = v0;
            *(float4*)(hc + 4) = v1;
        }
    }
    __syncthreads();            // hT final before gemm2 reads
}

// GEMM2: kdst = hT^T @ W2 + b2. K-split 4 (kq), rows rg2*8..+8, cols c2..+3.
// Tree: kq1->A(ysT), kq3->B(hT, dead post-gloop); kq0+=A, kq2+=B->B; kq0+=B.
__device__ __forceinline__ void gemm2(float* hT, const float* W2g, float* A,
                                      float* kdst, const ull (&b2p)[4],
                                      int kq, int rg2, int cg2, int c2, int slot2) {
    ull acc[4][4];
#pragma unroll
    for (int p = 0; p < 4; p++)
#pragma unroll
        for (int q = 0; q < 4; q++) acc[p][q] = 0ULL;
    gloop(hT + kq * 128 * STR + rg2 * 8, W2g + (size_t)kq * 128 * D + c2, D, acc);
    __syncthreads();            // all hT reads done; hT reusable as scratch B

    if (kq == 1) sts_acc(A + slot2 * SLOT, acc);
    if (kq == 3) sts_acc(hT + slot2 * SLOT, acc);
    __syncthreads();
    if (kq == 0) lds_add_acc(A + slot2 * SLOT, acc);
    if (kq == 2) { lds_add_acc(hT + slot2 * SLOT, acc); sts_acc(hT + slot2 * SLOT, acc); }
    __syncthreads();
    if (kq == 0) {
        lds_add_acc(hT + slot2 * SLOT, acc);
        const int rot = cg2 & 3;
#pragma unroll
        for (int i = 0; i < 4; i++) {
            int q = (i + rot) & 3;
            ulonglong2 o;
            o.x = add2(acc[0][q], b2p[q]);
            o.y = add2(acc[1][q], b2p[q]);
            float* kc = kdst + (c2 + q) * STR + rg2 * 8;
            *(ulonglong2*)(kc) = o;
            o.x = add2(acc[2][q], b2p[q]);
            o.y = add2(acc[3][q], b2p[q]);
            *(ulonglong2*)(kc + 4) = o;
        }
    }
    __syncthreads();
}

// dst: thread handles col d = tid>>1, half hf = tid&1 (8 floats)
__device__ __forceinline__ void combine(float* dst, const float* ysrc, const float* kbase,
                                        const float (&cf)[6], int cnt, int tid) {
    const int off = (tid >> 1) * STR + (tid & 1) * 8;
    ulonglong2 e01 = *(const ulonglong2*)(ysrc + off);
    ulonglong2 e23 = *(const ulonglong2*)(ysrc + off + 4);
    ull e[4] = {e01.x, e01.y, e23.x, e23.y};
#pragma unroll
    for (int j = 0; j < 6; j++) {
        if (j < cnt) {
            ull c = pack2(cf[j]);
            const float* kr = kbase + j * KT_STRIDE + off;
            ulonglong2 k01 = *(const ulonglong2*)(kr);
            ulonglong2 k23 = *(const ulonglong2*)(kr + 4);
            e[0] = fma2(c, k01.x, e[0]); e[1] = fma2(c, k01.y, e[1]);
            e[2] = fma2(c, k23.x, e[2]); e[3] = fma2(c, k23.y, e[3]);
        }
    }
    ulonglong2 o;
    o.x = e[0]; o.y = e[1]; *(ulonglong2*)(dst + off)     = o;
    o.x = e[2]; o.y = e[3]; *(ulonglong2*)(dst + off + 4) = o;
}

__global__ void __launch_bounds__(THREADS, 1)
node_ode_kernel(const float* __restrict__ x0, const float* __restrict__ t,
                const float* __restrict__ W1, const float* __restrict__ b1,
                const float* __restrict__ W2, const float* __restrict__ b2,
                const float* __restrict__ Wc1, const float* __restrict__ bc1,
                const float* __restrict__ Wc2, const float* __restrict__ bc2,
                float* __restrict__ out) {
    extern __shared__ float sm[];
    float* yT  = sm + OFF_YT;
    float* ysT = sm + OFF_YST;   // stage input / GEMM2 scratch A
    float* hT  = sm + OFF_HT;    // h / gemm1 scratch / gemm2 scratch B
    float* kT  = sm + OFF_KT;

    const int tid = threadIdx.x;
    // GEMM1 mapping: K-split 2 x 2 row-groups x 128 column-groups
    const int kh  = tid >> 8;
    const int rg  = (tid >> 7) & 1;
    const int cg  = tid & 127;
    const int c0  = cg * 4;
    const int slot1 = rg * 128 + cg;
    // GEMM2 mapping: K-split 4 x 2 row-groups x 64 column-groups
    const int kq  = tid >> 7;
    const int rg2 = (tid >> 6) & 1;
    const int cg2 = tid & 63;
    const int c2  = cg2 * 4;
    const int slot2 = rg2 * 64 + cg2;
    const int rowBase = blockIdx.x * ROWS;

    // transpose x0 tile into yT[k][row]
    if (tid < 256) {
        const int d = tid;
#pragma unroll
        for (int r = 0; r < ROWS; r++)
            yT[d * STR + r] = x0[(size_t)(rowBase + r) * D + d];
    }

    float b1r[4];
    {
        float4 u = *(const float4*)(b1 + c0);
        b1r[0] = u.x; b1r[1] = u.y; b1r[2] = u.z; b1r[3] = u.w;
    }
    ull b2p[4];
#pragma unroll
    for (int q = 0; q < 4; q++) b2p[q] = pack2(b2[c2 + q]);

    float tv[TPTS];
#pragma unroll
    for (int i = 0; i < TPTS; i++) tv[i] = t[i];

    __syncthreads();

    // dopri5 tableau
    const float A1[1] = {0.2f};
    const float A2[2] = {3.0f/40.0f, 9.0f/40.0f};
    const float A3[3] = {44.0f/45.0f, -56.0f/15.0f, 32.0f/9.0f};
    const float A4[4] = {19372.0f/6561.0f, -25360.0f/2187.0f, 64448.0f/6561.0f, -212.0f/729.0f};
    const float A5[5] = {9017.0f/3168.0f, -355.0f/33.0f, 46732.0f/5247.0f, 49.0f/176.0f, -5103.0f/18656.0f};
    const float B6[6] = {35.0f/384.0f, 0.0f, 500.0f/1113.0f, 125.0f/192.0f, -2187.0f/6784.0f, 11.0f/84.0f};
    const float* Arows[5] = {A1, A2, A3, A4, A5};

#pragma unroll 1
    for (int iv = 0; iv < TPTS - 1; iv++) {
        const float dt = (tv[iv + 1] - tv[iv]) * 0.25f;   // SUBSTEPS = 4
#pragma unroll 1
        for (int ss = 0; ss < 4; ss++) {
            // stage 1: k1 = f(y)
            gemm1(yT, W1, hT, b1r, kh, rg, cg, c0, slot1);
            gemm2(hT, W2, ysT, kT, b2p, kq, rg2, cg2, c2, slot2);
            // stages 2..6
#pragma unroll 1
            for (int s = 1; s < 6; s++) {
                float cf[6];
#pragma unroll
                for (int j = 0; j < 6; j++) cf[j] = (j < s) ? dt * Arows[s - 1][j] : 0.0f;
                combine(ysT, yT, kT, cf, s, tid);
                __syncthreads();
                gemm1(ysT, W1, hT, b1r, kh, rg, cg, c0, slot1);
                gemm2(hT, W2, ysT, kT + s * KT_STRIDE, b2p, kq, rg2, cg2, c2, slot2);
            }
            // final update: y += dt * sum b_i k_i
            float cf[6];
#pragma unroll
            for (int j = 0; j < 6; j++) cf[j] = dt * B6[j];
            combine(yT, yT, kT, cf, 6, tid);
            __syncthreads();
        }
    }

    // classifier head: h2 = relu(y @ Wc1 + bc1) -> reuse hT as [16 x 64]
    if (tid < 256) {
        const int r  = tid >> 4;
        const int cc = (tid & 15) * 4;
        float4 bb = *(const float4*)(bc1 + cc);
        float a0 = bb.x, a1 = bb.y, a2 = bb.z, a3 = bb.w;
#pragma unroll 4
        for (int k = 0; k < D; k++) {
            float a = yT[k * STR + r];
            float4 w = *(const float4*)(Wc1 + k * 64 + cc);
            a0 = fmaf(a, w.x, a0); a1 = fmaf(a, w.y, a1);
            a2 = fmaf(a, w.z, a2); a3 = fmaf(a, w.w, a3);
        }
        float4 o;
        o.x = fmaxf(a0, 0.0f); o.y = fmaxf(a1, 0.0f);
        o.z = fmaxf(a2, 0.0f); o.w = fmaxf(a3, 0.0f);
        *(float4*)(hT + r * 64 + cc) = o;
    }
    __syncthreads();
    // logits = h2 @ Wc2 + bc2, [16 x 10]
    if (tid < ROWS * NCLS) {
        const int r = tid / NCLS;
        const int c = tid - r * NCLS;
        float s = bc2[c];
#pragma unroll 8
        for (int k = 0; k < 64; k++)
            s = fmaf(hT[r * 64 + k], Wc2[k * NCLS + c], s);
        out[(size_t)(rowBase + r) * NCLS + c] = s;
    }
}

extern "C" void kernel_launch(void* const* d_in, const int* in_sizes, int n_in,
                              void* d_out, int out_size) {
    const float* x0  = (const float*)d_in[0];
    const float* t   = (const float*)d_in[1];
    const float* W1  = (const float*)d_in[2];
    const float* b1  = (const float*)d_in[3];
    const float* W2  = (const float*)d_in[4];
    const float* b2  = (const float*)d_in[5];
    const float* Wc1 = (const float*)d_in[6];
    const float* bc1 = (const float*)d_in[7];
    const float* Wc2 = (const float*)d_in[8];
    const float* bc2 = (const float*)d_in[9];
    float* out = (float*)d_out;

    static bool attr_set = false;
    if (!attr_set) {
        cudaFuncSetAttribute(node_ode_kernel,
                             cudaFuncAttributeMaxDynamicSharedMemorySize, SMEM_BYTES);
        attr_set = true;
    }
    node_ode_kernel<<<2048 / ROWS, THREADS, SMEM_BYTES>>>(
        x0, t, W1, b1, W2, b2, Wc1, bc1, Wc2, bc2, out);
}

// round 14
// speedup vs baseline: 3.1889x; 1.0345x over previous
#include <cuda_runtime.h>
#include <cstdint>

using ull = unsigned long long;

static constexpr int D = 256, H = 512, NCLS = 10, TPTS = 8;
static constexpr int ROWS = 16, THREADS = 256;
static constexpr int STR = 20;                 // padded floats per transposed row (16 used)
// smem layout (floats)
static constexpr int OFF_YT  = 0;              // 256*20 = 5120
static constexpr int OFF_YST = 256 * STR;      // stage input / GEMM2 scratch A
static constexpr int OFF_HT  = OFF_YST + 256 * STR;   // h / gemm1 scratch / gemm2 scratch B
static constexpr int OFF_KT  = OFF_HT + 512 * STR;
static constexpr int KT_STRIDE = 256 * STR;    // 5120 floats per k-stage
static constexpr int SMEM_FLOATS = OFF_KT + 6 * KT_STRIDE;   // 51200
static constexpr int SMEM_BYTES  = SMEM_FLOATS * 4;          // 204800

__device__ __forceinline__ ull fma2(ull a, ull b, ull c) {
    ull d; asm("fma.rn.f32x2 %0, %1, %2, %3;" : "=l"(d) : "l"(a), "l"(b), "l"(c)); return d;
}
__device__ __forceinline__ ull add2(ull a, ull b) {
    ull d; asm("add.rn.f32x2 %0, %1, %2;" : "=l"(d) : "l"(a), "l"(b)); return d;
}
__device__ __forceinline__ ull pack2(float x) {
    ull r; asm("mov.b64 %0, {%1, %1};" : "=l"(r) : "f"(x)); return r;
}
__device__ __forceinline__ float2 u2f(ull v) {
    float2 r; asm("mov.b64 {%0, %1}, %2;" : "=f"(r.x), "=f"(r.y) : "l"(v)); return r;
}
__device__ __forceinline__ float tanhfast(float x) {
    float e = __expf(2.0f * x);
    return 1.0f - __fdividef(2.0f, e + 1.0f);
}

// 2-k block: R=8 rows (4 packed pairs), C=8 cols; weights preloaded (4 float4)
__device__ __forceinline__ void block2(const float* actT, const float4* w, ull (&acc)[4][8]) {
#pragma unroll
    for (int j = 0; j < 2; j++) {
        const float* row = actT + j * STR;
        ulonglong2 a01 = *(const ulonglong2*)(row);
        ulonglong2 a23 = *(const ulonglong2*)(row + 4);
        ull a[4] = {a01.x, a01.y, a23.x, a23.y};
        float4 w0 = w[2 * j], w1 = w[2 * j + 1];
        ull bq[8] = {pack2(w0.x), pack2(w0.y), pack2(w0.z), pack2(w0.w),
                     pack2(w1.x), pack2(w1.y), pack2(w1.z), pack2(w1.w)};
#pragma unroll
        for (int p = 0; p < 4; p++)
#pragma unroll
            for (int q = 0; q < 8; q++)
                acc[p][q] = fma2(a[p], bq[q], acc[p][q]);
    }
}

// 128 k's; weights from gmem row stride ws (8 consecutive cols = 2 LDG.128/k)
__device__ __forceinline__ void gloop128(const float* actT, const float* wp, int ws,
                                         ull (&acc)[4][8]) {
    float4 wA[4], wB[4];
#pragma unroll
    for (int j = 0; j < 2; j++) {
        wA[2 * j]     = *(const float4*)(wp + j * ws);
        wA[2 * j + 1] = *(const float4*)(wp + j * ws + 4);
    }
#pragma unroll 1
    for (int b = 0; b < 64; b += 2) {
        const float* w1p = wp + (b + 1) * 2 * ws;
#pragma unroll
        for (int j = 0; j < 2; j++) {
            wB[2 * j]     = *(const float4*)(w1p + j * ws);
            wB[2 * j + 1] = *(const float4*)(w1p + j * ws + 4);
        }
        block2(actT + b * 2 * STR, wA, acc);
        if (b + 2 < 64) {
            const float* w2p = wp + (b + 2) * 2 * ws;
#pragma unroll
            for (int j = 0; j < 2; j++) {
                wA[2 * j]     = *(const float4*)(w2p + j * ws);
                wA[2 * j + 1] = *(const float4*)(w2p + j * ws + 4);
            }
        }
        block2(actT + (b + 1) * 2 * STR, wB, acc);
    }
}

// 68-float padded scratch slots (stride ≡ 4 mod 32 banks → conflict-free .128)
__device__ __forceinline__ void sts_acc(float* base, const ull (&acc)[4][8]) {
#pragma unroll
    for (int q = 0; q < 8; q++) {
        ulonglong2 o;
        o.x = acc[0][q]; o.y = acc[1][q];
        *(ulonglong2*)(base + q * 8) = o;
        o.x = acc[2][q]; o.y = acc[3][q];
        *(ulonglong2*)(base + q * 8 + 4) = o;
    }
}
__device__ __forceinline__ void lds_add_acc(const float* base, ull (&acc)[4][8]) {
#pragma unroll
    for (int q = 0; q < 8; q++) {
        ulonglong2 v0 = *(const ulonglong2*)(base + q * 8);
        ulonglong2 v1 = *(const ulonglong2*)(base + q * 8 + 4);
        acc[0][q] = add2(acc[0][q], v0.x);
        acc[1][q] = add2(acc[1][q], v0.y);
        acc[2][q] = add2(acc[2][q], v1.x);
        acc[3][q] = add2(acc[3][q], v1.y);
    }
}

// GEMM1: hT = tanh(actT^T @ W1 + b1). K-split 2 (kh), rows rg*8..+8, cols c0..+7.
// Partials staged in hT's own region (dead); WAR barrier before final writes.
// NOTE: epilogue q-loop is STATIC (no rotation) — dynamic acc indexing spills.
__device__ __forceinline__ void gemm1(const float* actT, const float* W1g, float* hT,
                                      const float (&b1r)[8], int kh, int rg, int c0,
                                      int slot1) {
    ull acc[4][8];
#pragma unroll
    for (int p = 0; p < 4; p++)
#pragma unroll
        for (int q = 0; q < 8; q++) acc[p][q] = 0ULL;
    gloop128(actT + kh * 128 * STR + rg * 8, W1g + (size_t)kh * 128 * H + c0, H, acc);

    if (kh == 1) sts_acc(hT + slot1 * 68, acc);
    __syncthreads();
    if (kh == 0) lds_add_acc(hT + slot1 * 68, acc);
    __syncthreads();            // WAR: scratch reads done before final hT writes
    if (kh == 0) {
#pragma unroll
        for (int q = 0; q < 8; q++) {
            float2 f0 = u2f(acc[0][q]), f1 = u2f(acc[1][q]);
            float2 f2 = u2f(acc[2][q]), f3 = u2f(acc[3][q]);
            float b = b1r[q];
            float4 v0, v1;
            v0.x = tanhfast(f0.x + b); v0.y = tanhfast(f0.y + b);
            v0.z = tanhfast(f1.x + b); v0.w = tanhfast(f1.y + b);
            v1.x = tanhfast(f2.x + b); v1.y = tanhfast(f2.y + b);
            v1.z = tanhfast(f3.x + b); v1.w = tanhfast(f3.y + b);
            float* hc = hT + (c0 + q) * STR + rg * 8;
            *(float4*)(hc)     = v0;
            *(float4*)(hc + 4) = v1;
        }
    }
    __syncthreads();            // hT final before gemm2 reads
}

// GEMM2: kdst = hT^T @ W2 + b2. K-split 4 (kq), rows rg2*8..+8, cols c2..+7.
// Tree reduction: kq1->A(ysT), kq3->B(hT, dead post-gloop); kq0+=A, kq2+=B->B; kq0+=B.
__device__ __forceinline__ void gemm2(float* hT, const float* W2g, float* A,
                                      float* kdst, const ull (&b2p)[8],
                                      int kq, int rg2, int c2, int slot2) {
    ull acc[4][8];
#pragma unroll
    for (int p = 0; p < 4; p++)
#pragma unroll
        for (int q = 0; q < 8; q++) acc[p][q] = 0ULL;
    gloop128(hT + kq * 128 * STR + rg2 * 8, W2g + (size_t)kq * 128 * D + c2, D, acc);
    __syncthreads();            // all hT reads done; hT reusable as scratch B

    if (kq == 1) sts_acc(A + slot2 * 68, acc);
    if (kq == 3) sts_acc(hT + slot2 * 68, acc);
    __syncthreads();
    if (kq == 0) lds_add_acc(A + slot2 * 68, acc);
    if (kq == 2) { lds_add_acc(hT + slot2 * 68, acc); sts_acc(hT + slot2 * 68, acc); }
    __syncthreads();
    if (kq == 0) {
        lds_add_acc(hT + slot2 * 68, acc);
#pragma unroll
        for (int q = 0; q < 8; q++) {
            ulonglong2 o;
            o.x = add2(acc[0][q], b2p[q]);
            o.y = add2(acc[1][q], b2p[q]);
            float* kc = kdst + (c2 + q) * STR + rg2 * 8;
            *(ulonglong2*)(kc) = o;
            o.x = add2(acc[2][q], b2p[q]);
            o.y = add2(acc[3][q], b2p[q]);
            *(ulonglong2*)(kc + 4) = o;
        }
    }
    __syncthreads();
}

// dst col d = ysrc col d + sum_{j<cnt} cf[j] * kT[j] col d   (thread d = tid)
__device__ __forceinline__ void combine(float* dst, const float* ysrc, const float* kbase,
                                        const float (&cf)[6], int cnt, int tid) {
    const int off = tid * STR;
    ulonglong2 e01 = *(const ulonglong2*)(ysrc + off);
    ulonglong2 e23 = *(const ulonglong2*)(ysrc + off + 4);
    ulonglong2 e45 = *(const ulonglong2*)(ysrc + off + 8);
    ulonglong2 e67 = *(const ulonglong2*)(ysrc + off + 12);
    ull e[8] = {e01.x, e01.y, e23.x, e23.y, e45.x, e45.y, e67.x, e67.y};
#pragma unroll
    for (int j = 0; j < 6; j++) {
        if (j < cnt) {
            ull c = pack2(cf[j]);
            const float* kr = kbase + j * KT_STRIDE + off;
            ulonglong2 k01 = *(const ulonglong2*)(kr);
            ulonglong2 k23 = *(const ulonglong2*)(kr + 4);
            ulonglong2 k45 = *(const ulonglong2*)(kr + 8);
            ulonglong2 k67 = *(const ulonglong2*)(kr + 12);
            e[0] = fma2(c, k01.x, e[0]); e[1] = fma2(c, k01.y, e[1]);
            e[2] = fma2(c, k23.x, e[2]); e[3] = fma2(c, k23.y, e[3]);
            e[4] = fma2(c, k45.x, e[4]); e[5] = fma2(c, k45.y, e[5]);
            e[6] = fma2(c, k67.x, e[6]); e[7] = fma2(c, k67.y, e[7]);
        }
    }
    ulonglong2 o;
    o.x = e[0]; o.y = e[1]; *(ulonglong2*)(dst + off)      = o;
    o.x = e[2]; o.y = e[3]; *(ulonglong2*)(dst + off + 4)  = o;
    o.x = e[4]; o.y = e[5]; *(ulonglong2*)(dst + off + 8)  = o;
    o.x = e[6]; o.y = e[7]; *(ulonglong2*)(dst + off + 12) = o;
}

__global__ void __launch_bounds__(THREADS, 1)
node_ode_kernel(const float* __restrict__ x0, const float* __restrict__ t,
                const float* __restrict__ W1, const float* __restrict__ b1,
                const float* __restrict__ W2, const float* __restrict__ b2,
                const float* __restrict__ Wc1, const float* __restrict__ bc1,
                const float* __restrict__ Wc2, const float* __restrict__ bc2,
                float* __restrict__ out) {
    extern __shared__ float sm[];
    float* yT  = sm + OFF_YT;
    float* ysT = sm + OFF_YST;   // stage input / GEMM2 scratch A
    float* hT  = sm + OFF_HT;    // h / gemm1 scratch / gemm2 scratch B
    float* kT  = sm + OFF_KT;

    const int tid = threadIdx.x;
    // GEMM1 mapping
    const int kh  = tid >> 7;
    const int rg  = (tid >> 6) & 1;
    const int cg  = tid & 63;
    const int c0  = cg * 8;
    const int slot1 = rg * 64 + cg;
    // GEMM2 mapping
    const int kq  = tid >> 6;
    const int rg2 = (tid >> 5) & 1;
    const int cg2 = tid & 31;
    const int c2  = cg2 * 8;
    const int slot2 = rg2 * 32 + cg2;
    const int rowBase = blockIdx.x * ROWS;

    // transpose x0 tile into yT[k][row]
    {
        const int d = tid;
#pragma unroll
        for (int r = 0; r < ROWS; r++)
            yT[d * STR + r] = x0[(size_t)(rowBase + r) * D + d];
    }

    float b1r[8];
    {
        float4 u = *(const float4*)(b1 + c0);
        float4 v = *(const float4*)(b1 + c0 + 4);
        b1r[0] = u.x; b1r[1] = u.y; b1r[2] = u.z; b1r[3] = u.w;
        b1r[4] = v.x; b1r[5] = v.y; b1r[6] = v.z; b1r[7] = v.w;
    }
    ull b2p[8];
#pragma unroll
    for (int q = 0; q < 8; q++) b2p[q] = pack2(b2[c2 + q]);

    float tv[TPTS];
#pragma unroll
    for (int i = 0; i < TPTS; i++) tv[i] = t[i];

    __syncthreads();

    // dopri5 tableau
    const float A1[1] = {0.2f};
    const float A2[2] = {3.0f/40.0f, 9.0f/40.0f};
    const float A3[3] = {44.0f/45.0f, -56.0f/15.0f, 32.0f/9.0f};
    const float A4[4] = {19372.0f/6561.0f, -25360.0f/2187.0f, 64448.0f/6561.0f, -212.0f/729.0f};
    const float A5[5] = {9017.0f/3168.0f, -355.0f/33.0f, 46732.0f/5247.0f, 49.0f/176.0f, -5103.0f/18656.0f};
    const float B6[6] = {35.0f/384.0f, 0.0f, 500.0f/1113.0f, 125.0f/192.0f, -2187.0f/6784.0f, 11.0f/84.0f};
    const float* Arows[5] = {A1, A2, A3, A4, A5};

#pragma unroll 1
    for (int iv = 0; iv < TPTS - 1; iv++) {
        const float dt = (tv[iv + 1] - tv[iv]) * 0.25f;   // SUBSTEPS = 4
#pragma unroll 1
        for (int ss = 0; ss < 4; ss++) {
            // stage 1: k1 = f(y)
            gemm1(yT, W1, hT, b1r, kh, rg, c0, slot1);
            gemm2(hT, W2, ysT, kT, b2p, kq, rg2, c2, slot2);
            // stages 2..6
#pragma unroll 1
            for (int s = 1; s < 6; s++) {
                float cf[6];
#pragma unroll
                for (int j = 0; j < 6; j++) cf[j] = (j < s) ? dt * Arows[s - 1][j] : 0.0f;
                combine(ysT, yT, kT, cf, s, tid);
                __syncthreads();
                gemm1(ysT, W1, hT, b1r, kh, rg, c0, slot1);
                gemm2(hT, W2, ysT, kT + s * KT_STRIDE, b2p, kq, rg2, c2, slot2);
            }
            // final update: y += dt * sum b_i k_i
            float cf[6];
#pragma unroll
            for (int j = 0; j < 6; j++) cf[j] = dt * B6[j];
            combine(yT, yT, kT, cf, 6, tid);
            __syncthreads();
        }
    }

    // classifier head: h2 = relu(y @ Wc1 + bc1) -> reuse hT as [16 x 64]
    {
        const int r  = tid >> 4;
        const int cc = (tid & 15) * 4;
        float4 bb = *(const float4*)(bc1 + cc);
        float a0 = bb.x, a1 = bb.y, a2 = bb.z, a3 = bb.w;
#pragma unroll 4
        for (int k = 0; k < D; k++) {
            float a = yT[k * STR + r];
            float4 w = *(const float4*)(Wc1 + k * 64 + cc);
            a0 = fmaf(a, w.x, a0); a1 = fmaf(a, w.y, a1);
            a2 = fmaf(a, w.z, a2); a3 = fmaf(a, w.w, a3);
        }
        float4 o;
        o.x = fmaxf(a0, 0.0f); o.y = fmaxf(a1, 0.0f);
        o.z = fmaxf(a2, 0.0f); o.w = fmaxf(a3, 0.0f);
        *(float4*)(hT + r * 64 + cc) = o;
    }
    __syncthreads();
    // logits = h2 @ Wc2 + bc2, [16 x 10]
    if (tid < ROWS * NCLS) {
        const int r = tid / NCLS;
        const int c = tid - r * NCLS;
        float s = bc2[c];
#pragma unroll 8
        for (int k = 0; k < 64; k++)
            s = fmaf(hT[r * 64 + k], Wc2[k * NCLS + c], s);
        out[(size_t)(rowBase + r) * NCLS + c] = s;
    }
}

extern "C" void kernel_launch(void* const* d_in, const int* in_sizes, int n_in,
                              void* d_out, int out_size) {
    const float* x0  = (const float*)d_in[0];
    const float* t   = (const float*)d_in[1];
    const float* W1  = (const float*)d_in[2];
    const float* b1  = (const float*)d_in[3];
    const float* W2  = (const float*)d_in[4];
    const float* b2  = (const float*)d_in[5];
    const float* Wc1 = (const float*)d_in[6];
    const float* bc1 = (const float*)d_in[7];
    const float* Wc2 = (const float*)d_in[8];
    const float* bc2 = (const float*)d_in[9];
    float* out = (float*)d_out;

    static bool attr_set = false;
    if (!attr_set) {
        cudaFuncSetAttribute(node_ode_kernel,
                             cudaFuncAttributeMaxDynamicSharedMemorySize, SMEM_BYTES);
        attr_set = true;
    }
    node_ode_kernel<<<2048 / ROWS, THREADS, SMEM_BYTES>>>(
        x0, t, W1, b1, W2, b2, Wc1, bc1, Wc2, bc2, out);
}

// round 15
// speedup vs baseline: 3.3877x; 1.0624x over previous
#include <cuda_runtime.h>
#include <cstdint>

using ull = unsigned long long;

static constexpr int D = 256, H = 512, NCLS = 10, TPTS = 8;
static constexpr int ROWS = 16, THREADS = 256;
static constexpr int STR = 20;                 // padded floats per transposed row (16 used)
// smem layout (floats)
static constexpr int OFF_YT  = 0;              // 256*20 = 5120
static constexpr int OFF_YST = 256 * STR;      // stage input / GEMM2 scratch A
static constexpr int OFF_HT  = OFF_YST + 256 * STR;   // h / gemm1 scratch / gemm2 scratch B
static constexpr int OFF_KT  = OFF_HT + 512 * STR;
static constexpr int KT_STRIDE = 256 * STR;    // 5120 floats per k-stage
static constexpr int SMEM_FLOATS = OFF_KT + 6 * KT_STRIDE;   // 51200
static constexpr int SMEM_BYTES  = SMEM_FLOATS * 4;          // 204800

__device__ __forceinline__ ull fma2(ull a, ull b, ull c) {
    ull d; asm("fma.rn.f32x2 %0, %1, %2, %3;" : "=l"(d) : "l"(a), "l"(b), "l"(c)); return d;
}
__device__ __forceinline__ ull add2(ull a, ull b) {
    ull d; asm("add.rn.f32x2 %0, %1, %2;" : "=l"(d) : "l"(a), "l"(b)); return d;
}
__device__ __forceinline__ ull pack2(float x) {
    ull r; asm("mov.b64 %0, {%1, %1};" : "=l"(r) : "f"(x)); return r;
}
__device__ __forceinline__ float2 u2f(ull v) {
    float2 r; asm("mov.b64 {%0, %1}, %2;" : "=f"(r.x), "=f"(r.y) : "l"(v)); return r;
}
__device__ __forceinline__ float tanhfast(float x) {
    float e = __expf(2.0f * x);
    return 1.0f - __fdividef(2.0f, e + 1.0f);
}

// 2-k block: R=8 rows (4 packed pairs), C=8 cols (two 4-col groups);
// weights preloaded (w[2j] = low group, w[2j+1] = high group)
__device__ __forceinline__ void block2(const float* actT, const float4* w, ull (&acc)[4][8]) {
#pragma unroll
    for (int j = 0; j < 2; j++) {
        const float* row = actT + j * STR;
        ulonglong2 a01 = *(const ulonglong2*)(row);
        ulonglong2 a23 = *(const ulonglong2*)(row + 4);
        ull a[4] = {a01.x, a01.y, a23.x, a23.y};
        float4 w0 = w[2 * j], w1 = w[2 * j + 1];
        ull bq[8] = {pack2(w0.x), pack2(w0.y), pack2(w0.z), pack2(w0.w),
                     pack2(w1.x), pack2(w1.y), pack2(w1.z), pack2(w1.w)};
#pragma unroll
        for (int p = 0; p < 4; p++)
#pragma unroll
            for (int q = 0; q < 8; q++)
                acc[p][q] = fma2(a[p], bq[q], acc[p][q]);
    }
}

// 128 k's; weights from gmem row stride ws. Two col groups: wp0 (cols c..c+3)
// and wp1 (cols c+half..c+half+3) — each LDG.128 is warp-contiguous.
__device__ __forceinline__ void gloop128(const float* actT, const float* wp0,
                                         const float* wp1, int ws, ull (&acc)[4][8]) {
    float4 wA[4], wB[4];
#pragma unroll
    for (int j = 0; j < 2; j++) {
        wA[2 * j]     = *(const float4*)(wp0 + j * ws);
        wA[2 * j + 1] = *(const float4*)(wp1 + j * ws);
    }
#pragma unroll 1
    for (int b = 0; b < 64; b += 2) {
        const int o1 = (b + 1) * 2 * ws;
#pragma unroll
        for (int j = 0; j < 2; j++) {
            wB[2 * j]     = *(const float4*)(wp0 + o1 + j * ws);
            wB[2 * j + 1] = *(const float4*)(wp1 + o1 + j * ws);
        }
        block2(actT + b * 2 * STR, wA, acc);
        if (b + 2 < 64) {
            const int o2 = (b + 2) * 2 * ws;
#pragma unroll
            for (int j = 0; j < 2; j++) {
                wA[2 * j]     = *(const float4*)(wp0 + o2 + j * ws);
                wA[2 * j + 1] = *(const float4*)(wp1 + o2 + j * ws);
            }
        }
        block2(actT + (b + 1) * 2 * STR, wB, acc);
    }
}

// 68-float padded scratch slots (stride ≡ 4 mod 32 banks → conflict-free .128)
__device__ __forceinline__ void sts_acc(float* base, const ull (&acc)[4][8]) {
#pragma unroll
    for (int q = 0; q < 8; q++) {
        ulonglong2 o;
        o.x = acc[0][q]; o.y = acc[1][q];
        *(ulonglong2*)(base + q * 8) = o;
        o.x = acc[2][q]; o.y = acc[3][q];
        *(ulonglong2*)(base + q * 8 + 4) = o;
    }
}
__device__ __forceinline__ void lds_add_acc(const float* base, ull (&acc)[4][8]) {
#pragma unroll
    for (int q = 0; q < 8; q++) {
        ulonglong2 v0 = *(const ulonglong2*)(base + q * 8);
        ulonglong2 v1 = *(const ulonglong2*)(base + q * 8 + 4);
        acc[0][q] = add2(acc[0][q], v0.x);
        acc[1][q] = add2(acc[1][q], v0.y);
        acc[2][q] = add2(acc[2][q], v1.x);
        acc[3][q] = add2(acc[3][q], v1.y);
    }
}

// GEMM1: hT = tanh(actT^T @ W1 + b1). K-split 2 (kh), rows rg*8..+8,
// cols {c0..c0+3} U {c0+256..c0+259}. Static epilogue indexing (no rotation).
__device__ __forceinline__ void gemm1(const float* actT, const float* W1g, float* hT,
                                      const float (&b1r)[8], int kh, int rg, int c0,
                                      int slot1) {
    ull acc[4][8];
#pragma unroll
    for (int p = 0; p < 4; p++)
#pragma unroll
        for (int q = 0; q < 8; q++) acc[p][q] = 0ULL;
    const float* wbase = W1g + (size_t)kh * 128 * H;
    gloop128(actT + kh * 128 * STR + rg * 8, wbase + c0, wbase + c0 + 256, H, acc);

    if (kh == 1) sts_acc(hT + slot1 * 68, acc);
    __syncthreads();
    if (kh == 0) lds_add_acc(hT + slot1 * 68, acc);
    __syncthreads();            // WAR: scratch reads done before final hT writes
    if (kh == 0) {
#pragma unroll
        for (int q = 0; q < 8; q++) {
            const int col = (q < 4) ? (c0 + q) : (c0 + 256 + (q - 4));
            float2 f0 = u2f(acc[0][q]), f1 = u2f(acc[1][q]);
            float2 f2 = u2f(acc[2][q]), f3 = u2f(acc[3][q]);
            float b = b1r[q];
            float4 v0, v1;
            v0.x = tanhfast(f0.x + b); v0.y = tanhfast(f0.y + b);
            v0.z = tanhfast(f1.x + b); v0.w = tanhfast(f1.y + b);
            v1.x = tanhfast(f2.x + b); v1.y = tanhfast(f2.y + b);
            v1.z = tanhfast(f3.x + b); v1.w = tanhfast(f3.y + b);
            float* hc = hT + col * STR + rg * 8;
            *(float4*)(hc)     = v0;
            *(float4*)(hc + 4) = v1;
        }
    }
    __syncthreads();            // hT final before gemm2 reads
}

// GEMM2: kdst = hT^T @ W2 + b2. K-split 4 (kq), rows rg2*8..+8,
// cols {c2..c2+3} U {c2+128..c2+131}. Tree reduction via ysT (A) and hT (B).
__device__ __forceinline__ void gemm2(float* hT, const float* W2g, float* A,
                                      float* kdst, const ull (&b2p)[8],
                                      int kq, int rg2, int c2, int slot2) {
    ull acc[4][8];
#pragma unroll
    for (int p = 0; p < 4; p++)
#pragma unroll
        for (int q = 0; q < 8; q++) acc[p][q] = 0ULL;
    const float* wbase = W2g + (size_t)kq * 128 * D;
    gloop128(hT + kq * 128 * STR + rg2 * 8, wbase + c2, wbase + c2 + 128, D, acc);
    __syncthreads();            // all hT reads done; hT reusable as scratch B

    if (kq == 1) sts_acc(A + slot2 * 68, acc);
    if (kq == 3) sts_acc(hT + slot2 * 68, acc);
    __syncthreads();
    if (kq == 0) lds_add_acc(A + slot2 * 68, acc);
    if (kq == 2) { lds_add_acc(hT + slot2 * 68, acc); sts_acc(hT + slot2 * 68, acc); }
    __syncthreads();
    if (kq == 0) {
        lds_add_acc(hT + slot2 * 68, acc);
#pragma unroll
        for (int q = 0; q < 8; q++) {
            const int col = (q < 4) ? (c2 + q) : (c2 + 128 + (q - 4));
            ulonglong2 o;
            o.x = add2(acc[0][q], b2p[q]);
            o.y = add2(acc[1][q], b2p[q]);
            float* kc = kdst + col * STR + rg2 * 8;
            *(ulonglong2*)(kc) = o;
            o.x = add2(acc[2][q], b2p[q]);
            o.y = add2(acc[3][q], b2p[q]);
            *(ulonglong2*)(kc + 4) = o;
        }
    }
    __syncthreads();
}

// dst col d = ysrc col d + sum_{j<cnt} cf[j] * kT[j] col d   (thread d = tid)
__device__ __forceinline__ void combine(float* dst, const float* ysrc, const float* kbase,
                                        const float (&cf)[6], int cnt, int tid) {
    const int off = tid * STR;
    ulonglong2 e01 = *(const ulonglong2*)(ysrc + off);
    ulonglong2 e23 = *(const ulonglong2*)(ysrc + off + 4);
    ulonglong2 e45 = *(const ulonglong2*)(ysrc + off + 8);
    ulonglong2 e67 = *(const ulonglong2*)(ysrc + off + 12);
    ull e[8] = {e01.x, e01.y, e23.x, e23.y, e45.x, e45.y, e67.x, e67.y};
#pragma unroll
    for (int j = 0; j < 6; j++) {
        if (j < cnt) {
            ull c = pack2(cf[j]);
            const float* kr = kbase + j * KT_STRIDE + off;
            ulonglong2 k01 = *(const ulonglong2*)(kr);
            ulonglong2 k23 = *(const ulonglong2*)(kr + 4);
            ulonglong2 k45 = *(const ulonglong2*)(kr + 8);
            ulonglong2 k67 = *(const ulonglong2*)(kr + 12);
            e[0] = fma2(c, k01.x, e[0]); e[1] = fma2(c, k01.y, e[1]);
            e[2] = fma2(c, k23.x, e[2]); e[3] = fma2(c, k23.y, e[3]);
            e[4] = fma2(c, k45.x, e[4]); e[5] = fma2(c, k45.y, e[5]);
            e[6] = fma2(c, k67.x, e[6]); e[7] = fma2(c, k67.y, e[7]);
        }
    }
    ulonglong2 o;
    o.x = e[0]; o.y = e[1]; *(ulonglong2*)(dst + off)      = o;
    o.x = e[2]; o.y = e[3]; *(ulonglong2*)(dst + off + 4)  = o;
    o.x = e[4]; o.y = e[5]; *(ulonglong2*)(dst + off + 8)  = o;
    o.x = e[6]; o.y = e[7]; *(ulonglong2*)(dst + off + 12) = o;
}

__global__ void __launch_bounds__(THREADS, 1)
node_ode_kernel(const float* __restrict__ x0, const float* __restrict__ t,
                const float* __restrict__ W1, const float* __restrict__ b1,
                const float* __restrict__ W2, const float* __restrict__ b2,
                const float* __restrict__ Wc1, const float* __restrict__ bc1,
                const float* __restrict__ Wc2, const float* __restrict__ bc2,
                float* __restrict__ out) {
    extern __shared__ float sm[];
    float* yT  = sm + OFF_YT;
    float* ysT = sm + OFF_YST;   // stage input / GEMM2 scratch A
    float* hT  = sm + OFF_HT;    // h / gemm1 scratch / gemm2 scratch B
    float* kT  = sm + OFF_KT;

    const int tid = threadIdx.x;
    // GEMM1 mapping
    const int kh  = tid >> 7;
    const int rg  = (tid >> 6) & 1;
    const int cg  = tid & 63;
    const int c0  = cg * 4;          // low col group (high group at +256)
    const int slot1 = rg * 64 + cg;
    // GEMM2 mapping
    const int kq  = tid >> 6;
    const int rg2 = (tid >> 5) & 1;
    const int cg2 = tid & 31;
    const int c2  = cg2 * 4;         // low col group (high group at +128)
    const int slot2 = rg2 * 32 + cg2;
    const int rowBase = blockIdx.x * ROWS;

    // transpose x0 tile into yT[k][row]
    {
        const int d = tid;
#pragma unroll
        for (int r = 0; r < ROWS; r++)
            yT[d * STR + r] = x0[(size_t)(rowBase + r) * D + d];
    }

    float b1r[8];
    {
        float4 u = *(const float4*)(b1 + c0);
        float4 v = *(const float4*)(b1 + c0 + 256);
        b1r[0] = u.x; b1r[1] = u.y; b1r[2] = u.z; b1r[3] = u.w;
        b1r[4] = v.x; b1r[5] = v.y; b1r[6] = v.z; b1r[7] = v.w;
    }
    ull b2p[8];
#pragma unroll
    for (int q = 0; q < 4; q++) {
        b2p[q]     = pack2(b2[c2 + q]);
        b2p[q + 4] = pack2(b2[c2 + 128 + q]);
    }

    float tv[TPTS];
#pragma unroll
    for (int i = 0; i < TPTS; i++) tv[i] = t[i];

    __syncthreads();

    // dopri5 tableau
    const float A1[1] = {0.2f};
    const float A2[2] = {3.0f/40.0f, 9.0f/40.0f};
    const float A3[3] = {44.0f/45.0f, -56.0f/15.0f, 32.0f/9.0f};
    const float A4[4] = {19372.0f/6561.0f, -25360.0f/2187.0f, 64448.0f/6561.0f, -212.0f/729.0f};
    const float A5[5] = {9017.0f/3168.0f, -355.0f/33.0f, 46732.0f/5247.0f, 49.0f/176.0f, -5103.0f/18656.0f};
    const float B6[6] = {35.0f/384.0f, 0.0f, 500.0f/1113.0f, 125.0f/192.0f, -2187.0f/6784.0f, 11.0f/84.0f};
    const float* Arows[5] = {A1, A2, A3, A4, A5};

#pragma unroll 1
    for (int iv = 0; iv < TPTS - 1; iv++) {
        const float dt = (tv[iv + 1] - tv[iv]) * 0.25f;   // SUBSTEPS = 4
#pragma unroll 1
        for (int ss = 0; ss < 4; ss++) {
            // stage 1: k1 = f(y)
            gemm1(yT, W1, hT, b1r, kh, rg, c0, slot1);
            gemm2(hT, W2, ysT, kT, b2p, kq, rg2, c2, slot2);
            // stages 2..6
#pragma unroll 1
            for (int s = 1; s < 6; s++) {
                float cf[6];
#pragma unroll
                for (int j = 0; j < 6; j++) cf[j] = (j < s) ? dt * Arows[s - 1][j] : 0.0f;
                combine(ysT, yT, kT, cf, s, tid);
                __syncthreads();
                gemm1(ysT, W1, hT, b1r, kh, rg, c0, slot1);
                gemm2(hT, W2, ysT, kT + s * KT_STRIDE, b2p, kq, rg2, c2, slot2);
            }
            // final update: y += dt * sum b_i k_i
            float cf[6];
#pragma unroll
            for (int j = 0; j < 6; j++) cf[j] = dt * B6[j];
            combine(yT, yT, kT, cf, 6, tid);
            __syncthreads();
        }
    }

    // classifier head: h2 = relu(y @ Wc1 + bc1) -> reuse hT as [16 x 64]
    {
        const int r  = tid >> 4;
        const int cc = (tid & 15) * 4;
        float4 bb = *(const float4*)(bc1 + cc);
        float a0 = bb.x, a1 = bb.y, a2 = bb.z, a3 = bb.w;
#pragma unroll 4
        for (int k = 0; k < D; k++) {
            float a = yT[k * STR + r];
            float4 w = *(const float4*)(Wc1 + k * 64 + cc);
            a0 = fmaf(a, w.x, a0); a1 = fmaf(a, w.y, a1);
            a2 = fmaf(a, w.z, a2); a3 = fmaf(a, w.w, a3);
        }
        float4 o;
        o.x = fmaxf(a0, 0.0f); o.y = fmaxf(a1, 0.0f);
        o.z = fmaxf(a2, 0.0f); o.w = fmaxf(a3, 0.0f);
        *(float4*)(hT + r * 64 + cc) = o;
    }
    __syncthreads();
    // logits = h2 @ Wc2 + bc2, [16 x 10]
    if (tid < ROWS * NCLS) {
        const int r = tid / NCLS;
        const int c = tid - r * NCLS;
        float s = bc2[c];
#pragma unroll 8
        for (int k = 0; k < 64; k++)
            s = fmaf(hT[r * 64 + k], Wc2[k * NCLS + c], s);
        out[(size_t)(rowBase + r) * NCLS + c] = s;
    }
}

extern "C" void kernel_launch(void* const* d_in, const int* in_sizes, int n_in,
                              void* d_out, int out_size) {
    const float* x0  = (const float*)d_in[0];
    const float* t   = (const float*)d_in[1];
    const float* W1  = (const float*)d_in[2];
    const float* b1  = (const float*)d_in[3];
    const float* W2  = (const float*)d_in[4];
    const float* b2  = (const float*)d_in[5];
    const float* Wc1 = (const float*)d_in[6];
    const float* bc1 = (const float*)d_in[7];
    const float* Wc2 = (const float*)d_in[8];
    const float* bc2 = (const float*)d_in[9];
    float* out = (float*)d_out;

    static bool attr_set = false;
    if (!attr_set) {
        cudaFuncSetAttribute(node_ode_kernel,
                             cudaFuncAttributeMaxDynamicSharedMemorySize, SMEM_BYTES);
        attr_set = true;
    }
    node_ode_kernel<<<2048 / ROWS, THREADS, SMEM_BYTES>>>(
        x0, t, W1, b1, W2, b2, Wc1, bc1, Wc2, bc2, out);
}

// round 16
// speedup vs baseline: 3.6292x; 1.0713x over previous
#include <cuda_runtime.h>
#include <cstdint>

using ull = unsigned long long;

static constexpr int D = 256, H = 512, NCLS = 10, TPTS = 8;
static constexpr int ROWS = 16, THREADS = 256;
static constexpr int STR = 20;                 // padded floats per transposed row (16 used)
// smem layout (floats)
static constexpr int OFF_YT  = 0;              // 256*20 = 5120
static constexpr int OFF_YST = 256 * STR;      // stage input / GEMM2 scratch A
static constexpr int OFF_HT  = OFF_YST + 256 * STR;   // h / gemm1 scratch / gemm2 scratch B
static constexpr int OFF_KT  = OFF_HT + 512 * STR;
static constexpr int KT_STRIDE = 256 * STR;    // 5120 floats per k-stage
static constexpr int SMEM_FLOATS = OFF_KT + 6 * KT_STRIDE;   // 51200
static constexpr int SMEM_BYTES  = SMEM_FLOATS * 4;          // 204800

__device__ __forceinline__ ull fma2(ull a, ull b, ull c) {
    ull d; asm("fma.rn.f32x2 %0, %1, %2, %3;" : "=l"(d) : "l"(a), "l"(b), "l"(c)); return d;
}
__device__ __forceinline__ ull add2(ull a, ull b) {
    ull d; asm("add.rn.f32x2 %0, %1, %2;" : "=l"(d) : "l"(a), "l"(b)); return d;
}
__device__ __forceinline__ ull pack2(float x) {
    ull r; asm("mov.b64 %0, {%1, %1};" : "=l"(r) : "f"(x)); return r;
}
__device__ __forceinline__ float2 u2f(ull v) {
    float2 r; asm("mov.b64 {%0, %1}, %2;" : "=f"(r.x), "=f"(r.y) : "l"(v)); return r;
}
// MUFU tanh (sm_75+): 1 op vs exp+rcp chain; max err ~1e-5 (tolerance 1e-3)
__device__ __forceinline__ float tanhfast(float x) {
    float r; asm("tanh.approx.f32 %0, %1;" : "=f"(r) : "f"(x)); return r;
}

// 4-k block: R=8 rows (4 packed pairs), C=8 cols (two 4-col groups);
// weights preloaded in w[8] (w[2j] = low group k j, w[2j+1] = high group k j)
__device__ __forceinline__ void block4(const float* actT, const float4* w, ull (&acc)[4][8]) {
#pragma unroll
    for (int j = 0; j < 4; j++) {
        const float* row = actT + j * STR;
        ulonglong2 a01 = *(const ulonglong2*)(row);
        ulonglong2 a23 = *(const ulonglong2*)(row + 4);
        ull a[4] = {a01.x, a01.y, a23.x, a23.y};
        float4 w0 = w[2 * j], w1 = w[2 * j + 1];
        ull bq[8] = {pack2(w0.x), pack2(w0.y), pack2(w0.z), pack2(w0.w),
                     pack2(w1.x), pack2(w1.y), pack2(w1.z), pack2(w1.w)};
#pragma unroll
        for (int p = 0; p < 4; p++)
#pragma unroll
            for (int q = 0; q < 8; q++)
                acc[p][q] = fma2(a[p], bq[q], acc[p][q]);
    }
}

// 128 k's = 32 blocks of 4 k. Weights from gmem row stride ws; col groups wp0/wp1
// (each LDG.128 warp-contiguous). Prefetch distance = 1 block4 (~256 cyc > L2 lat).
__device__ __forceinline__ void gloop128(const float* actT, const float* wp0,
                                         const float* wp1, int ws, ull (&acc)[4][8]) {
    float4 wA[8], wB[8];
#pragma unroll
    for (int j = 0; j < 4; j++) {
        wA[2 * j]     = *(const float4*)(wp0 + j * ws);
        wA[2 * j + 1] = *(const float4*)(wp1 + j * ws);
    }
#pragma unroll 1
    for (int b = 0; b < 32; b += 2) {
        const int o1 = (b + 1) * 4 * ws;
#pragma unroll
        for (int j = 0; j < 4; j++) {
            wB[2 * j]     = *(const float4*)(wp0 + o1 + j * ws);
            wB[2 * j + 1] = *(const float4*)(wp1 + o1 + j * ws);
        }
        block4(actT + b * 4 * STR, wA, acc);
        if (b + 2 < 32) {
            const int o2 = (b + 2) * 4 * ws;
#pragma unroll
            for (int j = 0; j < 4; j++) {
                wA[2 * j]     = *(const float4*)(wp0 + o2 + j * ws);
                wA[2 * j + 1] = *(const float4*)(wp1 + o2 + j * ws);
            }
        }
        block4(actT + (b + 1) * 4 * STR, wB, acc);
    }
}

// 68-float padded scratch slots (stride ≡ 4 mod 32 banks → conflict-free .128)
__device__ __forceinline__ void sts_acc(float* base, const ull (&acc)[4][8]) {
#pragma unroll
    for (int q = 0; q < 8; q++) {
        ulonglong2 o;
        o.x = acc[0][q]; o.y = acc[1][q];
        *(ulonglong2*)(base + q * 8) = o;
        o.x = acc[2][q]; o.y = acc[3][q];
        *(ulonglong2*)(base + q * 8 + 4) = o;
    }
}
__device__ __forceinline__ void lds_add_acc(const float* base, ull (&acc)[4][8]) {
#pragma unroll
    for (int q = 0; q < 8; q++) {
        ulonglong2 v0 = *(const ulonglong2*)(base + q * 8);
        ulonglong2 v1 = *(const ulonglong2*)(base + q * 8 + 4);
        acc[0][q] = add2(acc[0][q], v0.x);
        acc[1][q] = add2(acc[1][q], v0.y);
        acc[2][q] = add2(acc[2][q], v1.x);
        acc[3][q] = add2(acc[3][q], v1.y);
    }
}

// GEMM1: hT = tanh(actT^T @ W1 + b1). K-split 2 (kh), rows rg*8..+8,
// cols {c0..c0+3} U {c0+256..c0+259}. Static epilogue indexing (no rotation).
__device__ __forceinline__ void gemm1(const float* actT, const float* W1g, float* hT,
                                      const float (&b1r)[8], int kh, int rg, int c0,
                                      int slot1) {
    ull acc[4][8];
#pragma unroll
    for (int p = 0; p < 4; p++)
#pragma unroll
        for (int q = 0; q < 8; q++) acc[p][q] = 0ULL;
    const float* wbase = W1g + (size_t)kh * 128 * H;
    gloop128(actT + kh * 128 * STR + rg * 8, wbase + c0, wbase + c0 + 256, H, acc);

    if (kh == 1) sts_acc(hT + slot1 * 68, acc);
    __syncthreads();
    if (kh == 0) lds_add_acc(hT + slot1 * 68, acc);
    __syncthreads();            // WAR: scratch reads done before final hT writes
    if (kh == 0) {
#pragma unroll
        for (int q = 0; q < 8; q++) {
            const int col = (q < 4) ? (c0 + q) : (c0 + 256 + (q - 4));
            float2 f0 = u2f(acc[0][q]), f1 = u2f(acc[1][q]);
            float2 f2 = u2f(acc[2][q]), f3 = u2f(acc[3][q]);
            float b = b1r[q];
            float4 v0, v1;
            v0.x = tanhfast(f0.x + b); v0.y = tanhfast(f0.y + b);
            v0.z = tanhfast(f1.x + b); v0.w = tanhfast(f1.y + b);
            v1.x = tanhfast(f2.x + b); v1.y = tanhfast(f2.y + b);
            v1.z = tanhfast(f3.x + b); v1.w = tanhfast(f3.y + b);
            float* hc = hT + col * STR + rg * 8;
            *(float4*)(hc)     = v0;
            *(float4*)(hc + 4) = v1;
        }
    }
    __syncthreads();            // hT final before gemm2 reads
}

// GEMM2: kdst = hT^T @ W2 + b2. K-split 4 (kq), rows rg2*8..+8,
// cols {c2..c2+3} U {c2+128..c2+131}. Tree reduction via ysT (A) and hT (B).
__device__ __forceinline__ void gemm2(float* hT, const float* W2g, float* A,
                                      float* kdst, const ull (&b2p)[8],
                                      int kq, int rg2, int c2, int slot2) {
    ull acc[4][8];
#pragma unroll
    for (int p = 0; p < 4; p++)
#pragma unroll
        for (int q = 0; q < 8; q++) acc[p][q] = 0ULL;
    const float* wbase = W2g + (size_t)kq * 128 * D;
    gloop128(hT + kq * 128 * STR + rg2 * 8, wbase + c2, wbase + c2 + 128, D, acc);
    __syncthreads();            // all hT reads done; hT reusable as scratch B

    if (kq == 1) sts_acc(A + slot2 * 68, acc);
    if (kq == 3) sts_acc(hT + slot2 * 68, acc);
    __syncthreads();
    if (kq == 0) lds_add_acc(A + slot2 * 68, acc);
    if (kq == 2) { lds_add_acc(hT + slot2 * 68, acc); sts_acc(hT + slot2 * 68, acc); }
    __syncthreads();
    if (kq == 0) {
        lds_add_acc(hT + slot2 * 68, acc);
#pragma unroll
        for (int q = 0; q < 8; q++) {
            const int col = (q < 4) ? (c2 + q) : (c2 + 128 + (q - 4));
            ulonglong2 o;
            o.x = add2(acc[0][q], b2p[q]);
            o.y = add2(acc[1][q], b2p[q]);
            float* kc = kdst + col * STR + rg2 * 8;
            *(ulonglong2*)(kc) = o;
            o.x = add2(acc[2][q], b2p[q]);
            o.y = add2(acc[3][q], b2p[q]);
            *(ulonglong2*)(kc + 4) = o;
        }
    }
    __syncthreads();
}

// dst col d = ysrc col d + sum_{j<cnt} cf[j] * kT[j] col d   (thread d = tid)
__device__ __forceinline__ void combine(float* dst, const float* ysrc, const float* kbase,
                                        const float (&cf)[6], int cnt, int tid) {
    const int off = tid * STR;
    ulonglong2 e01 = *(const ulonglong2*)(ysrc + off);
    ulonglong2 e23 = *(const ulonglong2*)(ysrc + off + 4);
    ulonglong2 e45 = *(const ulonglong2*)(ysrc + off + 8);
    ulonglong2 e67 = *(const ulonglong2*)(ysrc + off + 12);
    ull e[8] = {e01.x, e01.y, e23.x, e23.y, e45.x, e45.y, e67.x, e67.y};
#pragma unroll
    for (int j = 0; j < 6; j++) {
        if (j < cnt) {
            ull c = pack2(cf[j]);
            const float* kr = kbase + j * KT_STRIDE + off;
            ulonglong2 k01 = *(const ulonglong2*)(kr);
            ulonglong2 k23 = *(const ulonglong2*)(kr + 4);
            ulonglong2 k45 = *(const ulonglong2*)(kr + 8);
            ulonglong2 k67 = *(const ulonglong2*)(kr + 12);
            e[0] = fma2(c, k01.x, e[0]); e[1] = fma2(c, k01.y, e[1]);
            e[2] = fma2(c, k23.x, e[2]); e[3] = fma2(c, k23.y, e[3]);
            e[4] = fma2(c, k45.x, e[4]); e[5] = fma2(c, k45.y, e[5]);
            e[6] = fma2(c, k67.x, e[6]); e[7] = fma2(c, k67.y, e[7]);
        }
    }
    ulonglong2 o;
    o.x = e[0]; o.y = e[1]; *(ulonglong2*)(dst + off)      = o;
    o.x = e[2]; o.y = e[3]; *(ulonglong2*)(dst + off + 4)  = o;
    o.x = e[4]; o.y = e[5]; *(ulonglong2*)(dst + off + 8)  = o;
    o.x = e[6]; o.y = e[7]; *(ulonglong2*)(dst + off + 12) = o;
}

__global__ void __launch_bounds__(THREADS, 1)
node_ode_kernel(const float* __restrict__ x0, const float* __restrict__ t,
                const float* __restrict__ W1, const float* __restrict__ b1,
                const float* __restrict__ W2, const float* __restrict__ b2,
                const float* __restrict__ Wc1, const float* __restrict__ bc1,
                const float* __restrict__ Wc2, const float* __restrict__ bc2,
                float* __restrict__ out) {
    extern __shared__ float sm[];
    float* yT  = sm + OFF_YT;
    float* ysT = sm + OFF_YST;   // stage input / GEMM2 scratch A
    float* hT  = sm + OFF_HT;    // h / gemm1 scratch / gemm2 scratch B
    float* kT  = sm + OFF_KT;

    const int tid = threadIdx.x;
    // GEMM1 mapping
    const int kh  = tid >> 7;
    const int rg  = (tid >> 6) & 1;
    const int cg  = tid & 63;
    const int c0  = cg * 4;          // low col group (high group at +256)
    const int slot1 = rg * 64 + cg;
    // GEMM2 mapping
    const int kq  = tid >> 6;
    const int rg2 = (tid >> 5) & 1;
    const int cg2 = tid & 31;
    const int c2  = cg2 * 4;         // low col group (high group at +128)
    const int slot2 = rg2 * 32 + cg2;
    const int rowBase = blockIdx.x * ROWS;

    // transpose x0 tile into yT[k][row]
    {
        const int d = tid;
#pragma unroll
        for (int r = 0; r < ROWS; r++)
            yT[d * STR + r] = x0[(size_t)(rowBase + r) * D + d];
    }

    float b1r[8];
    {
        float4 u = *(const float4*)(b1 + c0);
        float4 v = *(const float4*)(b1 + c0 + 256);
        b1r[0] = u.x; b1r[1] = u.y; b1r[2] = u.z; b1r[3] = u.w;
        b1r[4] = v.x; b1r[5] = v.y; b1r[6] = v.z; b1r[7] = v.w;
    }
    ull b2p[8];
#pragma unroll
    for (int q = 0; q < 4; q++) {
        b2p[q]     = pack2(b2[c2 + q]);
        b2p[q + 4] = pack2(b2[c2 + 128 + q]);
    }

    float tv[TPTS];
#pragma unroll
    for (int i = 0; i < TPTS; i++) tv[i] = t[i];

    __syncthreads();

    // dopri5 tableau
    const float A1[1] = {0.2f};
    const float A2[2] = {3.0f/40.0f, 9.0f/40.0f};
    const float A3[3] = {44.0f/45.0f, -56.0f/15.0f, 32.0f/9.0f};
    const float A4[4] = {19372.0f/6561.0f, -25360.0f/2187.0f, 64448.0f/6561.0f, -212.0f/729.0f};
    const float A5[5] = {9017.0f/3168.0f, -355.0f/33.0f, 46732.0f/5247.0f, 49.0f/176.0f, -5103.0f/18656.0f};
    const float B6[6] = {35.0f/384.0f, 0.0f, 500.0f/1113.0f, 125.0f/192.0f, -2187.0f/6784.0f, 11.0f/84.0f};
    const float* Arows[5] = {A1, A2, A3, A4, A5};

#pragma unroll 1
    for (int iv = 0; iv < TPTS - 1; iv++) {
        const float dt = (tv[iv + 1] - tv[iv]) * 0.25f;   // SUBSTEPS = 4
#pragma unroll 1
        for (int ss = 0; ss < 4; ss++) {
            // stage 1: k1 = f(y)
            gemm1(yT, W1, hT, b1r, kh, rg, c0, slot1);
            gemm2(hT, W2, ysT, kT, b2p, kq, rg2, c2, slot2);
            // stages 2..6
#pragma unroll 1
            for (int s = 1; s < 6; s++) {
                float cf[6];
#pragma unroll
                for (int j = 0; j < 6; j++) cf[j] = (j < s) ? dt * Arows[s - 1][j] : 0.0f;
                combine(ysT, yT, kT, cf, s, tid);
                __syncthreads();
                gemm1(ysT, W1, hT, b1r, kh, rg, c0, slot1);
                gemm2(hT, W2, ysT, kT + s * KT_STRIDE, b2p, kq, rg2, c2, slot2);
            }
            // final update: y += dt * sum b_i k_i
            float cf[6];
#pragma unroll
            for (int j = 0; j < 6; j++) cf[j] = dt * B6[j];
            combine(yT, yT, kT, cf, 6, tid);
            __syncthreads();
        }
    }

    // classifier head: h2 = relu(y @ Wc1 + bc1) -> reuse hT as [16 x 64]
    {
        const int r  = tid >> 4;
        const int cc = (tid & 15) * 4;
        float4 bb = *(const float4*)(bc1 + cc);
        float a0 = bb.x, a1 = bb.y, a2 = bb.z, a3 = bb.w;
#pragma unroll 4
        for (int k = 0; k < D; k++) {
            float a = yT[k * STR + r];
            float4 w = *(const float4*)(Wc1 + k * 64 + cc);
            a0 = fmaf(a, w.x, a0); a1 = fmaf(a, w.y, a1);
            a2 = fmaf(a, w.z, a2); a3 = fmaf(a, w.w, a3);
        }
        float4 o;
        o.x = fmaxf(a0, 0.0f); o.y = fmaxf(a1, 0.0f);
        o.z = fmaxf(a2, 0.0f); o.w = fmaxf(a3, 0.0f);
        *(float4*)(hT + r * 64 + cc) = o;
    }
    __syncthreads();
    // logits = h2 @ Wc2 + bc2, [16 x 10]
    if (tid < ROWS * NCLS) {
        const int r = tid / NCLS;
        const int c = tid - r * NCLS;
        float s = bc2[c];
#pragma unroll 8
        for (int k = 0; k < 64; k++)
            s = fmaf(hT[r * 64 + k], Wc2[k * NCLS + c], s);
        out[(size_t)(rowBase + r) * NCLS + c] = s;
    }
}

extern "C" void kernel_launch(void* const* d_in, const int* in_sizes, int n_in,
                              void* d_out, int out_size) {
    const float* x0  = (const float*)d_in[0];
    const float* t   = (const float*)d_in[1];
    const float* W1  = (const float*)d_in[2];
    const float* b1  = (const float*)d_in[3];
    const float* W2  = (const float*)d_in[4];
    const float* b2  = (const float*)d_in[5];
    const float* Wc1 = (const float*)d_in[6];
    const float* bc1 = (const float*)d_in[7];
    const float* Wc2 = (const float*)d_in[8];
    const float* bc2 = (const float*)d_in[9];
    float* out = (float*)d_out;

    static bool attr_set = false;
    if (!attr_set) {
        cudaFuncSetAttribute(node_ode_kernel,
                             cudaFuncAttributeMaxDynamicSharedMemorySize, SMEM_BYTES);
        attr_set = true;
    }
    node_ode_kernel<<<2048 / ROWS, THREADS, SMEM_BYTES>>>(
        x0, t, W1, b1, W2, b2, Wc1, bc1, Wc2, bc2, out);
}